// round 1
// baseline (speedup 1.0000x reference)
#include <cuda_runtime.h>
#include <math.h>

#define QDIM 1000
#define CDIM 80
#define QC   80000
#define KSEL 300
#define NTHREADS 1024
#define CAP 4096
#define NSAMP 2048
#define SAMP_RANK 40

// Monotone order-preserving map f32 -> u32 (total order, handles negatives).
__device__ __forceinline__ unsigned fkey(float x) {
    unsigned u = __float_as_uint(x);
    return u ^ (((unsigned)((int)u >> 31)) | 0x80000000u);
}

__global__ void __launch_bounds__(NTHREADS, 2)
rtdetr_post_kernel(const float* __restrict__ logits,
                   const float* __restrict__ boxes,
                   const float* __restrict__ sizes,
                   float* __restrict__ out, int B)
{
    __shared__ unsigned long long cand[CAP];
    __shared__ unsigned s_cut;
    __shared__ unsigned s_cnt;

    const int b   = blockIdx.x;
    const int tid = threadIdx.x;
    const float* lg = logits + (size_t)b * QC;

    // ---------------- Phase 0: sample 2048 keys, sort, pick conservative cut.
    // cut = 40th largest sample => expected survivors ~1.95% of 80000 ~ 1560,
    // P(survivors < 300) ~ 6 sigma, P(survivors > CAP) ~ 10 sigma.
    unsigned* samp = (unsigned*)cand;   // reuse candidate buffer
    for (int s = tid; s < NSAMP; s += NTHREADS) {
        int pos = (s * 625) >> 4;       // s * 80000 / 2048, strictly increasing
        samp[s] = fkey(lg[pos]);
    }
    __syncthreads();
    // bitonic sort, descending, NSAMP u32 keys
    for (unsigned k = 2; k <= NSAMP; k <<= 1) {
        for (unsigned j = k >> 1; j > 0; j >>= 1) {
            for (unsigned i = tid; i < NSAMP; i += NTHREADS) {
                unsigned ixj = i ^ j;
                if (ixj > i) {
                    unsigned a = samp[i], c = samp[ixj];
                    bool up = ((i & k) == 0);
                    if (up ? (a < c) : (a > c)) { samp[i] = c; samp[ixj] = a; }
                }
            }
            __syncthreads();
        }
    }
    if (tid == 0) { s_cut = samp[SAMP_RANK - 1]; s_cnt = 0; }
    __syncthreads();
    const unsigned cut = s_cut;

    // ---------------- Phase 1: single streaming pass, compact survivors.
    // Store (raw_float_bits << 32) | flat_index; ordering fixed later.
    const float4* lg4 = (const float4*)lg;
    for (int i = tid; i < QC / 4; i += NTHREADS) {
        float4 v = lg4[i];
        float xs[4] = {v.x, v.y, v.z, v.w};
        #pragma unroll
        for (int j = 0; j < 4; ++j) {
            float x = xs[j];
            if (fkey(x) >= cut) {
                unsigned p = atomicAdd(&s_cnt, 1u);
                if (p < CAP)
                    cand[p] = ((unsigned long long)__float_as_uint(x) << 32)
                              | (unsigned)(i * 4 + j);
            }
        }
    }
    __syncthreads();
    unsigned cnt = s_cnt; if (cnt > CAP) cnt = CAP;

    // ---------------- Phase 2: composite key = (f32 sigmoid bits, ~index).
    // Sigmoid computed in double, rounded to f32: ranks match jax.lax.top_k on
    // sigmoid scores; ties (equal f32 sigmoid) break toward the lower flat
    // index, exactly like XLA's stable top_k.
    for (unsigned i = tid; i < cnt; i += NTHREADS) {
        unsigned long long cc = cand[i];
        float x = __uint_as_float((unsigned)(cc >> 32));
        unsigned idx = (unsigned)cc;
        float sf = (float)(1.0 / (1.0 + exp(-(double)x)));
        cand[i] = ((unsigned long long)__float_as_uint(sf) << 32) | (~idx);
    }
    unsigned M = 1; while (M < cnt) M <<= 1; if (M < 512) M = 512;
    for (unsigned i = cnt + tid; i < M; i += NTHREADS) cand[i] = 0ull;
    __syncthreads();

    // bitonic sort, descending, M u64 composites
    for (unsigned k = 2; k <= M; k <<= 1) {
        for (unsigned j = k >> 1; j > 0; j >>= 1) {
            for (unsigned i = tid; i < M; i += NTHREADS) {
                unsigned ixj = i ^ j;
                if (ixj > i) {
                    unsigned long long a = cand[i], c = cand[ixj];
                    bool up = ((i & k) == 0);
                    if (up ? (a < c) : (a > c)) { cand[i] = c; cand[ixj] = a; }
                }
            }
            __syncthreads();
        }
    }

    // ---------------- Phase 3: emit top-300 (labels | boxes | scores).
    if (tid < KSEL) {
        unsigned long long cc = cand[tid];
        unsigned sig = (unsigned)(cc >> 32);
        unsigned idx = ~(unsigned)cc;
        if (idx >= QC) idx = 0;                 // safety (unreachable)
        unsigned q   = idx / CDIM;
        unsigned cls = idx - q * CDIM;

        float4 bx = ((const float4*)boxes)[(size_t)b * QDIM + q];
        float W = sizes[2 * b], H = sizes[2 * b + 1];

        int BK = B * KSEL;
        int o  = b * KSEL + tid;
        out[o] = (float)cls;                                   // labels
        float x1 = (bx.x - 0.5f * bx.z) * W;
        float y1 = (bx.y - 0.5f * bx.w) * H;
        float x2 = (bx.x + 0.5f * bx.z) * W;
        float y2 = (bx.y + 0.5f * bx.w) * H;
        ((float4*)(out + BK))[o] = make_float4(x1, y1, x2, y2); // boxes
        out[5 * BK + o] = __uint_as_float(sig);                 // scores
    }
}

extern "C" void kernel_launch(void* const* d_in, const int* in_sizes, int n_in,
                              void* d_out, int out_size) {
    const float* logits = (const float*)d_in[0];
    const float* boxes  = (const float*)d_in[1];
    const float* sizes  = (const float*)d_in[2];
    int B = in_sizes[0] / QC;
    rtdetr_post_kernel<<<B, NTHREADS>>>(logits, boxes, sizes, (float*)d_out, B);
}

// round 2
// speedup vs baseline: 1.0018x; 1.0018x over previous
#include <cuda_runtime.h>
#include <math.h>

#define QDIM 1000
#define CDIM 80
#define QC   80000
#define KSEL 300
#define NTHREADS 1024
#define CAP 4096
#define NSAMP 2048
#define SAMP_RANK 40

// Monotone order-preserving map f32 -> u32 (total order, handles negatives).
__device__ __forceinline__ unsigned fkey(float x) {
    unsigned u = __float_as_uint(x);
    return u ^ (((unsigned)((int)u >> 31)) | 0x80000000u);
}

__global__ void __launch_bounds__(NTHREADS, 2)
rtdetr_post_kernel(const float* __restrict__ logits,
                   const float* __restrict__ boxes,
                   const float* __restrict__ sizes,
                   float* __restrict__ out, int B)
{
    __shared__ unsigned long long cand[CAP];
    __shared__ unsigned s_cut;
    __shared__ unsigned s_cnt;

    const int b   = blockIdx.x;
    const int tid = threadIdx.x;
    const float* lg = logits + (size_t)b * QC;

    // ---------------- Phase 0: sample 2048 keys, sort, pick conservative cut.
    // cut = 40th largest sample => expected survivors ~1.95% of 80000 ~ 1560,
    // P(survivors < 300) ~ 6 sigma, P(survivors > CAP) ~ 10 sigma.
    unsigned* samp = (unsigned*)cand;   // reuse candidate buffer
    for (int s = tid; s < NSAMP; s += NTHREADS) {
        int pos = (s * 625) >> 4;       // s * 80000 / 2048, strictly increasing
        samp[s] = fkey(lg[pos]);
    }
    __syncthreads();
    // bitonic sort, descending, NSAMP u32 keys
    for (unsigned k = 2; k <= NSAMP; k <<= 1) {
        for (unsigned j = k >> 1; j > 0; j >>= 1) {
            for (unsigned i = tid; i < NSAMP; i += NTHREADS) {
                unsigned ixj = i ^ j;
                if (ixj > i) {
                    unsigned a = samp[i], c = samp[ixj];
                    bool up = ((i & k) == 0);
                    if (up ? (a < c) : (a > c)) { samp[i] = c; samp[ixj] = a; }
                }
            }
            __syncthreads();
        }
    }
    if (tid == 0) { s_cut = samp[SAMP_RANK - 1]; s_cnt = 0; }
    __syncthreads();
    const unsigned cut = s_cut;

    // ---------------- Phase 1: single streaming pass, compact survivors.
    // Store (raw_float_bits << 32) | flat_index; ordering fixed later.
    const float4* lg4 = (const float4*)lg;
    for (int i = tid; i < QC / 4; i += NTHREADS) {
        float4 v = lg4[i];
        float xs[4] = {v.x, v.y, v.z, v.w};
        #pragma unroll
        for (int j = 0; j < 4; ++j) {
            float x = xs[j];
            if (fkey(x) >= cut) {
                unsigned p = atomicAdd(&s_cnt, 1u);
                if (p < CAP)
                    cand[p] = ((unsigned long long)__float_as_uint(x) << 32)
                              | (unsigned)(i * 4 + j);
            }
        }
    }
    __syncthreads();
    unsigned cnt = s_cnt; if (cnt > CAP) cnt = CAP;

    // ---------------- Phase 2: composite key = (f32 sigmoid bits, ~index).
    // Sigmoid computed in double, rounded to f32: ranks match jax.lax.top_k on
    // sigmoid scores; ties (equal f32 sigmoid) break toward the lower flat
    // index, exactly like XLA's stable top_k.
    for (unsigned i = tid; i < cnt; i += NTHREADS) {
        unsigned long long cc = cand[i];
        float x = __uint_as_float((unsigned)(cc >> 32));
        unsigned idx = (unsigned)cc;
        float sf = (float)(1.0 / (1.0 + exp(-(double)x)));
        cand[i] = ((unsigned long long)__float_as_uint(sf) << 32) | (~idx);
    }
    unsigned M = 1; while (M < cnt) M <<= 1; if (M < 512) M = 512;
    for (unsigned i = cnt + tid; i < M; i += NTHREADS) cand[i] = 0ull;
    __syncthreads();

    // bitonic sort, descending, M u64 composites
    for (unsigned k = 2; k <= M; k <<= 1) {
        for (unsigned j = k >> 1; j > 0; j >>= 1) {
            for (unsigned i = tid; i < M; i += NTHREADS) {
                unsigned ixj = i ^ j;
                if (ixj > i) {
                    unsigned long long a = cand[i], c = cand[ixj];
                    bool up = ((i & k) == 0);
                    if (up ? (a < c) : (a > c)) { cand[i] = c; cand[ixj] = a; }
                }
            }
            __syncthreads();
        }
    }

    // ---------------- Phase 3: emit top-300 (labels | boxes | scores).
    if (tid < KSEL) {
        unsigned long long cc = cand[tid];
        unsigned sig = (unsigned)(cc >> 32);
        unsigned idx = ~(unsigned)cc;
        if (idx >= QC) idx = 0;                 // safety (unreachable)
        unsigned q   = idx / CDIM;
        unsigned cls = idx - q * CDIM;

        float4 bx = ((const float4*)boxes)[(size_t)b * QDIM + q];
        float W = sizes[2 * b], H = sizes[2 * b + 1];

        int BK = B * KSEL;
        int o  = b * KSEL + tid;
        out[o] = (float)cls;                                   // labels
        float x1 = (bx.x - 0.5f * bx.z) * W;
        float y1 = (bx.y - 0.5f * bx.w) * H;
        float x2 = (bx.x + 0.5f * bx.z) * W;
        float y2 = (bx.y + 0.5f * bx.w) * H;
        ((float4*)(out + BK))[o] = make_float4(x1, y1, x2, y2); // boxes
        out[5 * BK + o] = __uint_as_float(sig);                 // scores
    }
}

extern "C" void kernel_launch(void* const* d_in, const int* in_sizes, int n_in,
                              void* d_out, int out_size) {
    const float* logits = (const float*)d_in[0];
    const float* boxes  = (const float*)d_in[1];
    const float* sizes  = (const float*)d_in[2];
    int B = in_sizes[0] / QC;
    rtdetr_post_kernel<<<B, NTHREADS>>>(logits, boxes, sizes, (float*)d_out, B);
}

// round 3
// speedup vs baseline: 1.4644x; 1.4617x over previous
#include <cuda_runtime.h>
#include <math.h>

#define QDIM 1000
#define CDIM 80
#define QC   80000
#define KSEL 300
#define NTHREADS 1024
#define CAP  4096          // conservative-cut candidate buffer
#define CAP2 2048          // refined-cut buffer (sorted)
#define NSAMP 2048
#define SAMP_RANK 40
#define NBIN 2048
#define STREAM_ITERS ((QC/4 + NTHREADS - 1) / NTHREADS)  // 20

// Monotone order-preserving map f32 -> u32 (total order, handles negatives).
__device__ __forceinline__ unsigned fkey(float x) {
    unsigned u = __float_as_uint(x);
    return u ^ (((unsigned)((int)u >> 31)) | 0x80000000u);
}

// sigmoid-bits -> refine bucket (0 = best score). 2048-ulp buckets cover
// scores >= ~0.75; anything lower lumps into bucket 2047 (handled by sort cap).
__device__ __forceinline__ unsigned sig_bucket(unsigned sb) {
    int d = (int)(0x3F800000u - sb);
    if (d <= 0) return 0u;
    unsigned bkt = (unsigned)d >> 11;
    return bkt > 2047u ? 2047u : bkt;
}

__global__ void __launch_bounds__(NTHREADS, 2)
rtdetr_post_kernel(const float* __restrict__ logits,
                   const float* __restrict__ boxes,
                   const float* __restrict__ sizes,
                   float* __restrict__ out, int B)
{
    __shared__ unsigned long long cand[CAP];    // 32 KB
    __shared__ unsigned long long cand2[CAP2];  // 16 KB
    __shared__ unsigned hist[NBIN];             //  8 KB
    __shared__ unsigned s_cnt, s_cutb, s_cnt2;

    const int b    = blockIdx.x;
    const int tid  = threadIdx.x;
    const int lane = tid & 31;
    const float* lg = logits + (size_t)b * QC;

    // ---------------- Phase 0a: sampled histogram of fkey top-11-bits.
    hist[tid] = 0; hist[tid + NTHREADS] = 0;
    if (tid == 0) { s_cnt = 0; s_cnt2 = 0; }
    __syncthreads();
    // 16 coalesced blocks of 128 consecutive floats (iid data -> valid sample)
    {
        int s   = tid;                      // 1024 threads -> 2 samples each
        int pos0 = (s >> 7) * 5000 + (s & 127);
        int s2  = tid + NTHREADS;
        int pos1 = (s2 >> 7) * 5000 + (s2 & 127);
        atomicAdd(&hist[2047u - (fkey(__ldg(lg + pos0)) >> 21)], 1u);
        atomicAdd(&hist[2047u - (fkey(__ldg(lg + pos1)) >> 21)], 1u);
    }
    __syncthreads();

    // ---------------- Phase 0b: warp-0 segmented scan -> rough cut bucket.
    if (tid < 32) {
        unsigned s = 0;
        #pragma unroll 1
        for (int i = 0; i < 64; ++i)        // rotated index: bank-conflict-free
            s += hist[lane * 64 + ((i + lane) & 63)];
        unsigned sc = s;
        #pragma unroll
        for (int o = 1; o < 32; o <<= 1) {
            unsigned t = __shfl_up_sync(0xffffffffu, sc, o);
            if (lane >= o) sc += t;
        }
        unsigned vote = __ballot_sync(0xffffffffu, sc >= SAMP_RANK);
        int seg = vote ? (__ffs(vote) - 1) : 31;
        if (lane == seg) {
            unsigned excl = sc - s;
            int cb = seg * 64 + 63;
            for (int i = seg * 64; i < seg * 64 + 64; ++i) {
                excl += hist[i];
                if (excl >= SAMP_RANK) { cb = i; break; }
            }
            s_cutb = (unsigned)cb;
        }
    }
    __syncthreads();
    const unsigned cut = (2047u - s_cutb) << 21;   // keys >= cut survive
    // re-zero hist for the refine pass (published by the stream-end barrier)
    hist[tid] = 0; hist[tid + NTHREADS] = 0;

    // ---------------- Phase 1: single streaming pass, warp-aggregated compact.
    const float4* lg4 = (const float4*)lg;
    #pragma unroll 2
    for (int it = 0; it < STREAM_ITERS; ++it) {
        int i = tid + it * NTHREADS;
        bool inb = (i < QC / 4);
        float4 v = inb ? lg4[i] : make_float4(-1e30f, -1e30f, -1e30f, -1e30f);
        float xs[4] = {v.x, v.y, v.z, v.w};
        #pragma unroll
        for (int j = 0; j < 4; ++j) {
            float x = xs[j];
            bool pred = inb && (fkey(x) >= cut);
            unsigned m = __ballot_sync(0xffffffffu, pred);
            if (m) {
                int leader = __ffs(m) - 1;
                unsigned base = 0;
                if (lane == leader) base = atomicAdd(&s_cnt, (unsigned)__popc(m));
                base = __shfl_sync(0xffffffffu, base, leader);
                if (pred) {
                    unsigned p = base + __popc(m & ((1u << lane) - 1u));
                    if (p < CAP)
                        cand[p] = ((unsigned long long)__float_as_uint(x) << 32)
                                  | (unsigned)(i * 4 + j);
                }
            }
        }
    }
    __syncthreads();
    const unsigned cnt = min(s_cnt, (unsigned)CAP);

    // ---------------- Phase 2: sigmoid composite + refine histogram.
    // Composite = (f32 sigmoid bits << 32) | ~index : matches jax.lax.top_k
    // (sigmoid in double, rounded to f32; ties break toward lower index).
    for (unsigned i0 = 0; i0 < CAP; i0 += NTHREADS) {
        unsigned i = i0 + tid;
        if (i < cnt) {
            unsigned long long cc = cand[i];
            float x = __uint_as_float((unsigned)(cc >> 32));
            unsigned idx = (unsigned)cc;
            float sf = (float)(1.0 / (1.0 + exp(-(double)x)));
            unsigned sb = __float_as_uint(sf);
            cand[i] = ((unsigned long long)sb << 32) | (~idx);
            atomicAdd(&hist[sig_bucket(sb)], 1u);
        }
    }
    __syncthreads();

    // ---------------- Phase 2b: scan refine hist -> exact-bucket rank-300 cut.
    // Equal-sigmoid tie groups share a bucket -> inclusion is tie-atomic.
    if (tid < 32) {
        unsigned s = 0;
        #pragma unroll 1
        for (int i = 0; i < 64; ++i)
            s += hist[lane * 64 + ((i + lane) & 63)];
        unsigned sc = s;
        #pragma unroll
        for (int o = 1; o < 32; o <<= 1) {
            unsigned t = __shfl_up_sync(0xffffffffu, sc, o);
            if (lane >= o) sc += t;
        }
        unsigned vote = __ballot_sync(0xffffffffu, sc >= KSEL);
        int seg = vote ? (__ffs(vote) - 1) : 31;
        if (lane == seg) {
            unsigned excl = sc - s;
            int cb = seg * 64 + 63;
            for (int i = seg * 64; i < seg * 64 + 64; ++i) {
                excl += hist[i];
                if (excl >= KSEL) { cb = i; break; }
            }
            s_cutb = (unsigned)cb;
        }
    }
    __syncthreads();
    const unsigned cutb2 = s_cutb;

    // ---------------- Phase 3: refined compaction into cand2 (warp-aggregated).
    for (unsigned i0 = 0; i0 < CAP; i0 += NTHREADS) {
        unsigned i = i0 + tid;
        bool pred = false;
        unsigned long long cc = 0;
        if (i < cnt) {
            cc = cand[i];
            pred = sig_bucket((unsigned)(cc >> 32)) <= cutb2;
        }
        unsigned m = __ballot_sync(0xffffffffu, pred);
        if (m) {
            int leader = __ffs(m) - 1;
            unsigned base = 0;
            if (lane == leader) base = atomicAdd(&s_cnt2, (unsigned)__popc(m));
            base = __shfl_sync(0xffffffffu, base, leader);
            if (pred) {
                unsigned p = base + __popc(m & ((1u << lane) - 1u));
                if (p < CAP2) cand2[p] = cc;
            }
        }
    }
    __syncthreads();
    const unsigned cnt2 = min(s_cnt2, (unsigned)CAP2);

    // ---------------- Phase 4: bitonic sort (descending) of M >= cnt2 (>=512).
    unsigned M = 512; while (M < cnt2) M <<= 1;
    for (unsigned i = cnt2 + tid; i < M; i += NTHREADS) cand2[i] = 0ull;
    __syncthreads();
    for (unsigned k = 2; k <= M; k <<= 1) {
        for (unsigned j = k >> 1; j > 0; j >>= 1) {
            for (unsigned i = tid; i < M; i += NTHREADS) {
                unsigned ixj = i ^ j;
                if (ixj > i) {
                    unsigned long long a = cand2[i], c = cand2[ixj];
                    bool up = ((i & k) == 0);
                    if (up ? (a < c) : (a > c)) { cand2[i] = c; cand2[ixj] = a; }
                }
            }
            __syncthreads();
        }
    }

    // ---------------- Phase 5: emit top-300 (labels | boxes | scores).
    if (tid < KSEL) {
        unsigned long long cc = cand2[tid];
        unsigned sig = (unsigned)(cc >> 32);
        unsigned idx = ~(unsigned)cc;
        if (idx >= QC) idx = 0;                 // safety (unreachable)
        unsigned q   = idx / CDIM;
        unsigned cls = idx - q * CDIM;

        float4 bx = ((const float4*)boxes)[(size_t)b * QDIM + q];
        float W = sizes[2 * b], H = sizes[2 * b + 1];

        int BK = B * KSEL;
        int o  = b * KSEL + tid;
        out[o] = (float)cls;                                   // labels
        float x1 = (bx.x - 0.5f * bx.z) * W;
        float y1 = (bx.y - 0.5f * bx.w) * H;
        float x2 = (bx.x + 0.5f * bx.z) * W;
        float y2 = (bx.y + 0.5f * bx.w) * H;
        ((float4*)(out + BK))[o] = make_float4(x1, y1, x2, y2); // boxes
        out[5 * BK + o] = __uint_as_float(sig);                 // scores
    }
}

extern "C" void kernel_launch(void* const* d_in, const int* in_sizes, int n_in,
                              void* d_out, int out_size) {
    const float* logits = (const float*)d_in[0];
    const float* boxes  = (const float*)d_in[1];
    const float* sizes  = (const float*)d_in[2];
    int B = in_sizes[0] / QC;
    rtdetr_post_kernel<<<B, NTHREADS>>>(logits, boxes, sizes, (float*)d_out, B);
}

// round 4
// speedup vs baseline: 1.6651x; 1.1371x over previous
#include <cuda_runtime.h>
#include <math.h>

#define QDIM 1000
#define CDIM 80
#define QC   80000
#define KSEL 300
#define NTHREADS 1024
#define CAP  4096          // conservative-cut candidate buffer
#define CAP2 2048          // refined-cut buffer (sorted)
#define SAMP_RANK 40
#define NBIN 2048

// Monotone order-preserving map f32 -> u32 (total order, handles negatives).
__device__ __forceinline__ unsigned fkey(float x) {
    unsigned u = __float_as_uint(x);
    return u ^ (((unsigned)((int)u >> 31)) | 0x80000000u);
}

// sigmoid-bits -> refine bucket (0 = best score). 2048-ulp buckets cover
// scores >= ~0.75; anything lower lumps into bucket 2047.
__device__ __forceinline__ unsigned sig_bucket(unsigned sb) {
    int d = (int)(0x3F800000u - sb);
    if (d <= 0) return 0u;
    unsigned bkt = (unsigned)d >> 11;
    return bkt > 2047u ? 2047u : bkt;
}

__global__ void __launch_bounds__(NTHREADS, 2)
rtdetr_post_kernel(const float* __restrict__ logits,
                   const float* __restrict__ boxes,
                   const float* __restrict__ sizes,
                   float* __restrict__ out, int B)
{
    __shared__ unsigned long long cand[CAP];    // 32 KB
    __shared__ unsigned long long cand2[CAP2];  // 16 KB
    __shared__ unsigned hist[NBIN];             //  8 KB
    __shared__ unsigned s_cnt, s_cutb, s_cnt2;

    const int b    = blockIdx.x;
    const int tid  = threadIdx.x;
    const int lane = tid & 31;
    const float* lg = logits + (size_t)b * QC;

    // ---------------- Phase 0a: sampled histogram of fkey top-11-bits.
    hist[tid] = 0; hist[tid + NTHREADS] = 0;
    if (tid == 0) { s_cnt = 0; s_cnt2 = 0; }
    __syncthreads();
    // 16 coalesced blocks of 128 consecutive floats (iid data -> valid sample)
    {
        int s    = tid;
        int pos0 = (s >> 7) * 5000 + (s & 127);
        int s2   = tid + NTHREADS;
        int pos1 = (s2 >> 7) * 5000 + (s2 & 127);
        atomicAdd(&hist[2047u - (fkey(__ldg(lg + pos0)) >> 21)], 1u);
        atomicAdd(&hist[2047u - (fkey(__ldg(lg + pos1)) >> 21)], 1u);
    }
    __syncthreads();

    // ---------------- Phase 0b: warp-0 segmented scan -> rough cut bucket.
    // cut = ~rank-40-of-2048 sample => survivors ~1560 +- 250 (CAP=4096 safe).
    if (tid < 32) {
        unsigned s = 0;
        #pragma unroll 1
        for (int i = 0; i < 64; ++i)        // rotated: bank-conflict-free
            s += hist[lane * 64 + ((i + lane) & 63)];
        unsigned sc = s;
        #pragma unroll
        for (int o = 1; o < 32; o <<= 1) {
            unsigned t = __shfl_up_sync(0xffffffffu, sc, o);
            if (lane >= o) sc += t;
        }
        unsigned vote = __ballot_sync(0xffffffffu, sc >= SAMP_RANK);
        int seg = vote ? (__ffs(vote) - 1) : 31;
        if (lane == seg) {
            unsigned excl = sc - s;
            int cb = seg * 64 + 63;
            for (int i = seg * 64; i < seg * 64 + 64; ++i) {
                excl += hist[i];
                if (excl >= SAMP_RANK) { cb = i; break; }
            }
            s_cutb = (unsigned)cb;
        }
    }
    __syncthreads();
    const unsigned cut = (2047u - s_cutb) << 21;   // keys >= cut survive
    // re-zero hist for the refine pass (published by the stream-end barrier)
    hist[tid] = 0; hist[tid + NTHREADS] = 0;

    // ---------------- Phase 1: streaming pass, ballot-free compaction.
    // No per-element ballots: loads pipeline freely (MLP ~4-5). Only ~8% of
    // threads per iteration have any survivor; they do one shared atomic.
    const float4* lg4 = (const float4*)lg;
    #pragma unroll 4
    for (int i = tid; i < QC / 4; i += NTHREADS) {
        float4 v = lg4[i];
        unsigned k0 = fkey(v.x), k1 = fkey(v.y), k2 = fkey(v.z), k3 = fkey(v.w);
        int c = (k0 >= cut) + (k1 >= cut) + (k2 >= cut) + (k3 >= cut);
        if (c) {
            unsigned p = atomicAdd(&s_cnt, (unsigned)c);
            unsigned base = (unsigned)(i * 4);
            if (k0 >= cut) { if (p < CAP) cand[p] = ((unsigned long long)__float_as_uint(v.x) << 32) | (base + 0); ++p; }
            if (k1 >= cut) { if (p < CAP) cand[p] = ((unsigned long long)__float_as_uint(v.y) << 32) | (base + 1); ++p; }
            if (k2 >= cut) { if (p < CAP) cand[p] = ((unsigned long long)__float_as_uint(v.z) << 32) | (base + 2); ++p; }
            if (k3 >= cut) { if (p < CAP) cand[p] = ((unsigned long long)__float_as_uint(v.w) << 32) | (base + 3); ++p; }
        }
    }
    __syncthreads();
    const unsigned cnt = min(s_cnt, (unsigned)CAP);

    // ---------------- Phase 2: sigmoid composite + refine histogram.
    // Composite = (f32 sigmoid bits << 32) | ~index : matches jax.lax.top_k
    // (sigmoid in double, rounded to f32; ties break toward lower index).
    for (unsigned i = tid; i < cnt; i += NTHREADS) {
        unsigned long long cc = cand[i];
        float x = __uint_as_float((unsigned)(cc >> 32));
        unsigned idx = (unsigned)cc;
        float sf = (float)(1.0 / (1.0 + exp(-(double)x)));
        unsigned sb = __float_as_uint(sf);
        cand[i] = ((unsigned long long)sb << 32) | (~idx);
        atomicAdd(&hist[sig_bucket(sb)], 1u);
    }
    __syncthreads();

    // ---------------- Phase 2b: scan refine hist -> exact-bucket rank-300 cut.
    // Equal-sigmoid tie groups share a bucket -> inclusion is tie-atomic.
    if (tid < 32) {
        unsigned s = 0;
        #pragma unroll 1
        for (int i = 0; i < 64; ++i)
            s += hist[lane * 64 + ((i + lane) & 63)];
        unsigned sc = s;
        #pragma unroll
        for (int o = 1; o < 32; o <<= 1) {
            unsigned t = __shfl_up_sync(0xffffffffu, sc, o);
            if (lane >= o) sc += t;
        }
        unsigned vote = __ballot_sync(0xffffffffu, sc >= KSEL);
        int seg = vote ? (__ffs(vote) - 1) : 31;
        if (lane == seg) {
            unsigned excl = sc - s;
            int cb = seg * 64 + 63;
            for (int i = seg * 64; i < seg * 64 + 64; ++i) {
                excl += hist[i];
                if (excl >= KSEL) { cb = i; break; }
            }
            s_cutb = (unsigned)cb;
        }
    }
    __syncthreads();
    const unsigned cutb2 = s_cutb;

    // ---------------- Phase 3: refined compaction into cand2 (~300-350 hits).
    for (unsigned i = tid; i < cnt; i += NTHREADS) {
        unsigned long long cc = cand[i];
        if (sig_bucket((unsigned)(cc >> 32)) <= cutb2) {
            unsigned p = atomicAdd(&s_cnt2, 1u);
            if (p < CAP2) cand2[p] = cc;
        }
    }
    __syncthreads();
    const unsigned cnt2 = min(s_cnt2, (unsigned)CAP2);

    // ---------------- Phase 4: bitonic sort (descending), hybrid syncs.
    // Writer of element e at step j is thread e&~j: for j<32 (and both
    // neighbor steps <32) producer+consumer share a warp -> __syncwarp.
    unsigned M = 512; while (M < cnt2) M <<= 1;
    for (unsigned i = cnt2 + tid; i < M; i += NTHREADS) cand2[i] = 0ull;
    __syncthreads();
    const bool wok = (M <= (unsigned)NTHREADS);   // each thread owns <=1 slot
    for (unsigned k = 2; k <= M; k <<= 1) {
        for (unsigned j = k >> 1; j > 0; j >>= 1) {
            for (unsigned i = tid; i < M; i += NTHREADS) {
                unsigned ixj = i ^ j;
                if (ixj > i) {
                    unsigned long long a = cand2[i], c = cand2[ixj];
                    bool up = ((i & k) == 0);
                    if (up ? (a < c) : (a > c)) { cand2[i] = c; cand2[ixj] = a; }
                }
            }
            unsigned jn = (j > 1) ? (j >> 1) : k;   // next step's stride
            if (!wok || j >= 32 || jn >= 32) __syncthreads();
            else __syncwarp();
        }
    }

    // ---------------- Phase 5: emit top-300 (labels | boxes | scores).
    if (tid < KSEL) {
        unsigned long long cc = cand2[tid];
        unsigned sig = (unsigned)(cc >> 32);
        unsigned idx = ~(unsigned)cc;
        if (idx >= QC) idx = 0;                 // safety (unreachable)
        unsigned q   = idx / CDIM;
        unsigned cls = idx - q * CDIM;

        float4 bx = ((const float4*)boxes)[(size_t)b * QDIM + q];
        float W = sizes[2 * b], H = sizes[2 * b + 1];

        int BK = B * KSEL;
        int o  = b * KSEL + tid;
        out[o] = (float)cls;                                   // labels
        float x1 = (bx.x - 0.5f * bx.z) * W;
        float y1 = (bx.y - 0.5f * bx.w) * H;
        float x2 = (bx.x + 0.5f * bx.z) * W;
        float y2 = (bx.y + 0.5f * bx.w) * H;
        ((float4*)(out + BK))[o] = make_float4(x1, y1, x2, y2); // boxes
        out[5 * BK + o] = __uint_as_float(sig);                 // scores
    }
}

extern "C" void kernel_launch(void* const* d_in, const int* in_sizes, int n_in,
                              void* d_out, int out_size) {
    const float* logits = (const float*)d_in[0];
    const float* boxes  = (const float*)d_in[1];
    const float* sizes  = (const float*)d_in[2];
    int B = in_sizes[0] / QC;
    rtdetr_post_kernel<<<B, NTHREADS>>>(logits, boxes, sizes, (float*)d_out, B);
}